// round 11
// baseline (speedup 1.0000x reference)
#include <cuda_runtime.h>
#include <cuda_fp16.h>
#include <cuda_bf16.h>

// HashEncoder: 4-level dense-grid trilinear interpolation, F=4.
// R11 = R4 encode (measured best: 60.3us, regs=32, occ 86%) verbatim
//     + R8 feature-pair build_cells (measured best: 12.2us).
// fp16 cell records (64B/cell, values pre-scaled by 2^12). Per (cell,feature):
// 4 half2 groups g(dy*2+dx) = {c(dx,dy,z0), c(dx,dy,z1)}.
// Encode: 2 points per warp-slot (lane = q*16 + L*4 + f); one 16B gather per
// lane per slot (4 L1tex wavefronts/point = gather optimum); x/y lerps in
// half2 SIMD, final z lerp + 2^-12 rescale in fp32.
//
// Level meta: res={32,43,56,74}, offsets={0,32768,112280,287896}, total=693120.

#define NPARAMS 693120
#define VAL_SCALE 4096.0f
#define INV_VAL_SCALE (1.0f / 4096.0f)

__device__ __half g_cells_h[NPARAMS * 32];   // 44.4 MB scratch (64B/cell)

__constant__ int c_res[4] = {32, 43, 56, 74};
__constant__ int c_off[4] = {0, 32768, 112280, 287896};

// ---------------------------------------------------------------- preprocess table
// thread t = gbase*2 + fp : builds records for features {2fp, 2fp+1}.
// Reads 8 float2 (both features of each corner), writes 2 uint4 (32B).
__global__ void __launch_bounds__(256)
build_cells(const float* __restrict__ tab)
{
    int t = blockIdx.x * blockDim.x + threadIdx.x;
    if (t >= NPARAMS * 2) return;

    int gbase = t >> 1;
    int fp = t & 1;

    int L = (gbase >= 32768) + (gbase >= 112280) + (gbase >= 287896);
    int res  = c_res[L];
    int off  = c_off[L];
    int res2 = res * res;
    int local = gbase - off;

    int z   = local / res2;          // padding cells may exceed grid; clamp below
    int rem = local - z * res2;
    int y   = rem / res;
    int x   = rem - y * res;

    float2 v[4][2];                  // [g=dy*2+dx][dz] = (feat 2fp, feat 2fp+1)
#pragma unroll
    for (int g = 0; g < 4; ++g) {
        int xi = min(x + (g & 1), res - 1);
        int yi = min(y + (g >> 1), res - 1);
#pragma unroll
        for (int dz = 0; dz < 2; ++dz) {
            int zi = min(z + dz, res - 1);
            int idx = off + xi + yi * res + zi * res2;
            float2 w = __ldg((const float2*)&tab[idx * 4 + 2 * fp]);
            v[g][dz] = make_float2(w.x * VAL_SCALE, w.y * VAL_SCALE);
        }
    }

    uint4 r0, r1;
    {
        half2 h0 = __floats2half2_rn(v[0][0].x, v[0][1].x);
        half2 h1 = __floats2half2_rn(v[1][0].x, v[1][1].x);
        half2 h2 = __floats2half2_rn(v[2][0].x, v[2][1].x);
        half2 h3 = __floats2half2_rn(v[3][0].x, v[3][1].x);
        r0.x = *(unsigned*)&h0; r0.y = *(unsigned*)&h1;
        r0.z = *(unsigned*)&h2; r0.w = *(unsigned*)&h3;
    }
    {
        half2 h0 = __floats2half2_rn(v[0][0].y, v[0][1].y);
        half2 h1 = __floats2half2_rn(v[1][0].y, v[1][1].y);
        half2 h2 = __floats2half2_rn(v[2][0].y, v[2][1].y);
        half2 h3 = __floats2half2_rn(v[3][0].y, v[3][1].y);
        r1.x = *(unsigned*)&h0; r1.y = *(unsigned*)&h1;
        r1.z = *(unsigned*)&h2; r1.w = *(unsigned*)&h3;
    }

    uint4* dst = (uint4*)g_cells_h;
    dst[gbase * 4 + 2 * fp]     = r0;
    dst[gbase * 4 + 2 * fp + 1] = r1;
}

// ---------------------------------------------------------------- main pass
// R4 encode, verbatim.
template <bool GUARD>
__device__ __forceinline__ void
encode_body(const float* __restrict__ pos, float* __restrict__ out,
            const __half* __restrict__ cells_f, float s,
            int res, int res2, int off,
            int p0, int q, int lane, int n)
{
#pragma unroll
    for (int k = 0; k < 8; ++k) {
        int p = p0 + 2 * k + q;
        bool valid = true;
        if (GUARD) { valid = (p < n); if (!valid) p = n - 1; }

        float x = __ldg(&pos[3 * p + 0]);
        float y = __ldg(&pos[3 * p + 1]);
        float z = __ldg(&pos[3 * p + 2]);

        float px = fmaf(x, s, 0.5f);
        float py = fmaf(y, s, 0.5f);
        float pz = fmaf(z, s, 0.5f);
        float gx = floorf(px), gy = floorf(py), gz = floorf(pz);
        float fx = px - gx, fy = py - gy, fz = pz - gz;
        int ix = (int)gx, iy = (int)gy, iz = (int)gz;

        int gbase = off + ix + iy * res + iz * res2;

        // 16B: 4 half2 z-pair groups of this lane's feature.
        uint4 rec = __ldg((const uint4*)(cells_f + (size_t)gbase * 32));
        half2 g0 = *(half2*)&rec.x;   // (dx,dy)=(0,0), {z0,z1}
        half2 g1 = *(half2*)&rec.y;   // (1,0)
        half2 g2 = *(half2*)&rec.z;   // (0,1)
        half2 g3 = *(half2*)&rec.w;   // (1,1)

        half2 fx2 = __float2half2_rn(fx);
        half2 fy2 = __float2half2_rn(fy);

        half2 a = __hfma2(fx2, __hsub2(g1, g0), g0);   // y=0, both z
        half2 b = __hfma2(fx2, __hsub2(g3, g2), g2);   // y=1, both z
        half2 c = __hfma2(fy2, __hsub2(b, a), a);      // {z0, z1}

        float clo = __low2float(c);
        float chi = __high2float(c);
        float r = fmaf(fz, chi - clo, clo) * INV_VAL_SCALE;

        if (!GUARD || valid)
            out[(size_t)p0 * 16 + 32 * k + lane] = r;
    }
}

__global__ void __launch_bounds__(256)
encode_kernel(const float* __restrict__ pos, float* __restrict__ out,
              float4 scales, int n)
{
    const int lane = threadIdx.x & 31;
    const int warp = (blockIdx.x * blockDim.x + threadIdx.x) >> 5;
    const int p0 = warp * 16;
    if (p0 >= n) return;

    const int q = lane >> 4;            // point parity within slot
    const int L = (lane >> 2) & 3;      // level
    const int f = lane & 3;             // feature

    const float s = (L < 2) ? (L == 0 ? scales.x : scales.y)
                            : (L == 2 ? scales.z : scales.w);
    const int res  = c_res[L];
    const int res2 = res * res;
    const int off  = c_off[L];
    const __half* cells_f = g_cells_h + f * 8;

    if (p0 + 16 <= n)
        encode_body<false>(pos, out, cells_f, s, res, res2, off, p0, q, lane, n);
    else
        encode_body<true>(pos, out, cells_f, s, res, res2, off, p0, q, lane, n);
}

// ---------------------------------------------------------------- launcher
extern "C" void kernel_launch(void* const* d_in, const int* in_sizes, int n_in,
                              void* d_out, int out_size)
{
    const float* positions = (const float*)d_in[0];
    const float* table = (const float*)d_in[1];
    float* out = (float*)d_out;

    int n = in_sizes[0] / 3;

    // Level scales: double math, rounded to fp32 like JAX's weak promotion.
    double b = 1.3195079565048218;
    double p = 1.0;
    float s[4];
    for (int l = 0; l < 4; ++l) {
        s[l] = (float)(32.0 * p - 1.0);
        p *= b;
    }
    float4 scales = make_float4(s[0], s[1], s[2], s[3]);

    int bb = (NPARAMS * 2 + 255) / 256;
    build_cells<<<bb, 256>>>(table);

    int warps = (n + 15) / 16;
    int blocks = (warps * 32 + 255) / 256;
    encode_kernel<<<blocks, 256>>>(positions, out, scales, n);
}

// round 12
// speedup vs baseline: 1.2596x; 1.2596x over previous
#include <cuda_runtime.h>
#include <cuda_fp16.h>
#include <cuda_bf16.h>

// HashEncoder: 4-level dense-grid trilinear interpolation, F=4.
// R12 = R11 (R4-shape encode + feature-pair build) + cache-policy hints:
// positions via __ldcs (read-once, evict-first), output via __stcs
// (write-once streaming) so the 128MB output stream does not evict the
// 44MB cell table from L2 between gathers.
// fp16 cell records (64B/cell, values pre-scaled by 2^12). Per (cell,feature):
// 4 half2 groups g(dy*2+dx) = {c(dx,dy,z0), c(dx,dy,z1)}.
// Encode: 2 points per warp-slot (lane = q*16 + L*4 + f); one 16B gather per
// lane per slot (4 L1tex wavefronts/point = gather optimum).
//
// Level meta: res={32,43,56,74}, offsets={0,32768,112280,287896}, total=693120.

#define NPARAMS 693120
#define VAL_SCALE 4096.0f
#define INV_VAL_SCALE (1.0f / 4096.0f)

__device__ __half g_cells_h[NPARAMS * 32];   // 44.4 MB scratch (64B/cell)

__constant__ int c_res[4] = {32, 43, 56, 74};
__constant__ int c_off[4] = {0, 32768, 112280, 287896};

// ---------------------------------------------------------------- preprocess table
// thread t = gbase*2 + fp : builds records for features {2fp, 2fp+1}.
__global__ void __launch_bounds__(256)
build_cells(const float* __restrict__ tab)
{
    int t = blockIdx.x * blockDim.x + threadIdx.x;
    if (t >= NPARAMS * 2) return;

    int gbase = t >> 1;
    int fp = t & 1;

    int L = (gbase >= 32768) + (gbase >= 112280) + (gbase >= 287896);
    int res  = c_res[L];
    int off  = c_off[L];
    int res2 = res * res;
    int local = gbase - off;

    int z   = local / res2;          // padding cells may exceed grid; clamp below
    int rem = local - z * res2;
    int y   = rem / res;
    int x   = rem - y * res;

    float2 v[4][2];                  // [g=dy*2+dx][dz] = (feat 2fp, feat 2fp+1)
#pragma unroll
    for (int g = 0; g < 4; ++g) {
        int xi = min(x + (g & 1), res - 1);
        int yi = min(y + (g >> 1), res - 1);
#pragma unroll
        for (int dz = 0; dz < 2; ++dz) {
            int zi = min(z + dz, res - 1);
            int idx = off + xi + yi * res + zi * res2;
            float2 w = __ldg((const float2*)&tab[idx * 4 + 2 * fp]);
            v[g][dz] = make_float2(w.x * VAL_SCALE, w.y * VAL_SCALE);
        }
    }

    uint4 r0, r1;
    {
        half2 h0 = __floats2half2_rn(v[0][0].x, v[0][1].x);
        half2 h1 = __floats2half2_rn(v[1][0].x, v[1][1].x);
        half2 h2 = __floats2half2_rn(v[2][0].x, v[2][1].x);
        half2 h3 = __floats2half2_rn(v[3][0].x, v[3][1].x);
        r0.x = *(unsigned*)&h0; r0.y = *(unsigned*)&h1;
        r0.z = *(unsigned*)&h2; r0.w = *(unsigned*)&h3;
    }
    {
        half2 h0 = __floats2half2_rn(v[0][0].y, v[0][1].y);
        half2 h1 = __floats2half2_rn(v[1][0].y, v[1][1].y);
        half2 h2 = __floats2half2_rn(v[2][0].y, v[2][1].y);
        half2 h3 = __floats2half2_rn(v[3][0].y, v[3][1].y);
        r1.x = *(unsigned*)&h0; r1.y = *(unsigned*)&h1;
        r1.z = *(unsigned*)&h2; r1.w = *(unsigned*)&h3;
    }

    uint4* dst = (uint4*)g_cells_h;
    dst[gbase * 4 + 2 * fp]     = r0;
    dst[gbase * 4 + 2 * fp + 1] = r1;
}

// ---------------------------------------------------------------- main pass
template <bool GUARD>
__device__ __forceinline__ void
encode_body(const float* __restrict__ pos, float* __restrict__ out,
            const __half* __restrict__ cells_f, float s,
            int res, int res2, int off,
            int p0, int q, int lane, int n)
{
#pragma unroll
    for (int k = 0; k < 8; ++k) {
        int p = p0 + 2 * k + q;
        bool valid = true;
        if (GUARD) { valid = (p < n); if (!valid) p = n - 1; }

        // Positions: read-once stream, evict-first.
        float x = __ldcs(&pos[3 * p + 0]);
        float y = __ldcs(&pos[3 * p + 1]);
        float z = __ldcs(&pos[3 * p + 2]);

        float px = fmaf(x, s, 0.5f);
        float py = fmaf(y, s, 0.5f);
        float pz = fmaf(z, s, 0.5f);
        float gx = floorf(px), gy = floorf(py), gz = floorf(pz);
        float fx = px - gx, fy = py - gy, fz = pz - gz;
        int ix = (int)gx, iy = (int)gy, iz = (int)gz;

        int gbase = off + ix + iy * res + iz * res2;

        // 16B: 4 half2 z-pair groups of this lane's feature (keep cached).
        uint4 rec = __ldg((const uint4*)(cells_f + (size_t)gbase * 32));
        half2 g0 = *(half2*)&rec.x;   // (dx,dy)=(0,0), {z0,z1}
        half2 g1 = *(half2*)&rec.y;   // (1,0)
        half2 g2 = *(half2*)&rec.z;   // (0,1)
        half2 g3 = *(half2*)&rec.w;   // (1,1)

        half2 fx2 = __float2half2_rn(fx);
        half2 fy2 = __float2half2_rn(fy);

        half2 a = __hfma2(fx2, __hsub2(g1, g0), g0);   // y=0, both z
        half2 b = __hfma2(fx2, __hsub2(g3, g2), g2);   // y=1, both z
        half2 c = __hfma2(fy2, __hsub2(b, a), a);      // {z0, z1}

        float clo = __low2float(c);
        float chi = __high2float(c);
        float r = fmaf(fz, chi - clo, clo) * INV_VAL_SCALE;

        // Output: write-once stream, evict-first (protect cell table in L2).
        if (!GUARD || valid)
            __stcs(&out[(size_t)p0 * 16 + 32 * k + lane], r);
    }
}

__global__ void __launch_bounds__(256)
encode_kernel(const float* __restrict__ pos, float* __restrict__ out,
              float4 scales, int n)
{
    const int lane = threadIdx.x & 31;
    const int warp = (blockIdx.x * blockDim.x + threadIdx.x) >> 5;
    const int p0 = warp * 16;
    if (p0 >= n) return;

    const int q = lane >> 4;            // point parity within slot
    const int L = (lane >> 2) & 3;      // level
    const int f = lane & 3;             // feature

    const float s = (L < 2) ? (L == 0 ? scales.x : scales.y)
                            : (L == 2 ? scales.z : scales.w);
    const int res  = c_res[L];
    const int res2 = res * res;
    const int off  = c_off[L];
    const __half* cells_f = g_cells_h + f * 8;

    if (p0 + 16 <= n)
        encode_body<false>(pos, out, cells_f, s, res, res2, off, p0, q, lane, n);
    else
        encode_body<true>(pos, out, cells_f, s, res, res2, off, p0, q, lane, n);
}

// ---------------------------------------------------------------- launcher
extern "C" void kernel_launch(void* const* d_in, const int* in_sizes, int n_in,
                              void* d_out, int out_size)
{
    const float* positions = (const float*)d_in[0];
    const float* table = (const float*)d_in[1];
    float* out = (float*)d_out;

    int n = in_sizes[0] / 3;

    // Level scales: double math, rounded to fp32 like JAX's weak promotion.
    double b = 1.3195079565048218;
    double p = 1.0;
    float s[4];
    for (int l = 0; l < 4; ++l) {
        s[l] = (float)(32.0 * p - 1.0);
        p *= b;
    }
    float4 scales = make_float4(s[0], s[1], s[2], s[3]);

    int bb = (NPARAMS * 2 + 255) / 256;
    build_cells<<<bb, 256>>>(table);

    int warps = (n + 15) / 16;
    int blocks = (warps * 32 + 255) / 256;
    encode_kernel<<<blocks, 256>>>(positions, out, scales, n);
}

// round 13
// speedup vs baseline: 1.2939x; 1.0273x over previous
#include <cuda_runtime.h>
#include <cuda_fp16.h>
#include <cuda_bf16.h>

// HashEncoder: 4-level dense-grid trilinear interpolation, F=4.
// R13 (final shape) = R4-structure encode + feature-pair build + streaming
// cache hints + trunc-floor index math.
// fp16 cell records (64B/cell, values pre-scaled by 2^12). Per (cell,feature):
// 4 half2 groups g(dy*2+dx) = {c(dx,dy,z0), c(dx,dy,z1)}.
// Encode: 2 points per warp-slot (lane = q*16 + L*4 + f); ONE 16B gather per
// lane per slot -> 4 L1tex wavefronts/point (the gather optimum: 8 distinct
// cell lines covered by a single LDG.E.128). x/y lerps in half2 SIMD, final
// z lerp + 2^-12 rescale in fp32. Positions __ldcs (read-once), output __stcs
// (write-once; protects the 44MB cell table's L2 residency).
//
// Level meta: res={32,43,56,74}, offsets={0,32768,112280,287896}, total=693120.

#define NPARAMS 693120
#define VAL_SCALE 4096.0f
#define INV_VAL_SCALE (1.0f / 4096.0f)

__device__ __half g_cells_h[NPARAMS * 32];   // 44.4 MB scratch (64B/cell)

__constant__ int c_res[4] = {32, 43, 56, 74};
__constant__ int c_off[4] = {0, 32768, 112280, 287896};

// ---------------------------------------------------------------- preprocess table
// thread t = gbase*2 + fp : builds records for features {2fp, 2fp+1}.
__global__ void __launch_bounds__(256)
build_cells(const float* __restrict__ tab)
{
    int t = blockIdx.x * blockDim.x + threadIdx.x;
    if (t >= NPARAMS * 2) return;

    int gbase = t >> 1;
    int fp = t & 1;

    int L = (gbase >= 32768) + (gbase >= 112280) + (gbase >= 287896);
    int res  = c_res[L];
    int off  = c_off[L];
    int res2 = res * res;
    int local = gbase - off;

    int z   = local / res2;          // padding cells may exceed grid; clamp below
    int rem = local - z * res2;
    int y   = rem / res;
    int x   = rem - y * res;

    float2 v[4][2];                  // [g=dy*2+dx][dz] = (feat 2fp, feat 2fp+1)
#pragma unroll
    for (int g = 0; g < 4; ++g) {
        int xi = min(x + (g & 1), res - 1);
        int yi = min(y + (g >> 1), res - 1);
#pragma unroll
        for (int dz = 0; dz < 2; ++dz) {
            int zi = min(z + dz, res - 1);
            int idx = off + xi + yi * res + zi * res2;
            float2 w = __ldg((const float2*)&tab[idx * 4 + 2 * fp]);
            v[g][dz] = make_float2(w.x * VAL_SCALE, w.y * VAL_SCALE);
        }
    }

    uint4 r0, r1;
    {
        half2 h0 = __floats2half2_rn(v[0][0].x, v[0][1].x);
        half2 h1 = __floats2half2_rn(v[1][0].x, v[1][1].x);
        half2 h2 = __floats2half2_rn(v[2][0].x, v[2][1].x);
        half2 h3 = __floats2half2_rn(v[3][0].x, v[3][1].x);
        r0.x = *(unsigned*)&h0; r0.y = *(unsigned*)&h1;
        r0.z = *(unsigned*)&h2; r0.w = *(unsigned*)&h3;
    }
    {
        half2 h0 = __floats2half2_rn(v[0][0].y, v[0][1].y);
        half2 h1 = __floats2half2_rn(v[1][0].y, v[1][1].y);
        half2 h2 = __floats2half2_rn(v[2][0].y, v[2][1].y);
        half2 h3 = __floats2half2_rn(v[3][0].y, v[3][1].y);
        r1.x = *(unsigned*)&h0; r1.y = *(unsigned*)&h1;
        r1.z = *(unsigned*)&h2; r1.w = *(unsigned*)&h3;
    }

    uint4* dst = (uint4*)g_cells_h;
    dst[gbase * 4 + 2 * fp]     = r0;
    dst[gbase * 4 + 2 * fp + 1] = r1;
}

// ---------------------------------------------------------------- main pass
template <bool GUARD>
__device__ __forceinline__ void
encode_body(const float* __restrict__ pos, float* __restrict__ out,
            const __half* __restrict__ cells_f, float s,
            int res, int res2, int off,
            int p0, int q, int lane, int n)
{
#pragma unroll
    for (int k = 0; k < 8; ++k) {
        int p = p0 + 2 * k + q;
        bool valid = true;
        if (GUARD) { valid = (p < n); if (!valid) p = n - 1; }

        // Positions: read-once stream, evict-first.
        float x = __ldcs(&pos[3 * p + 0]);
        float y = __ldcs(&pos[3 * p + 1]);
        float z = __ldcs(&pos[3 * p + 2]);

        float px = fmaf(x, s, 0.5f);
        float py = fmaf(y, s, 0.5f);
        float pz = fmaf(z, s, 0.5f);
        // px,py,pz >= 0.5 always, so round-down int conversion == floor.
        int ix = __float2int_rd(px);
        int iy = __float2int_rd(py);
        int iz = __float2int_rd(pz);
        float fx = px - __int2float_rn(ix);
        float fy = py - __int2float_rn(iy);
        float fz = pz - __int2float_rn(iz);

        int gbase = off + ix + iy * res + iz * res2;

        // 16B: 4 half2 z-pair groups of this lane's feature (keep cached).
        uint4 rec = __ldg((const uint4*)(cells_f + (size_t)gbase * 32));
        half2 g0 = *(half2*)&rec.x;   // (dx,dy)=(0,0), {z0,z1}
        half2 g1 = *(half2*)&rec.y;   // (1,0)
        half2 g2 = *(half2*)&rec.z;   // (0,1)
        half2 g3 = *(half2*)&rec.w;   // (1,1)

        half2 fx2 = __float2half2_rn(fx);
        half2 fy2 = __float2half2_rn(fy);

        half2 a = __hfma2(fx2, __hsub2(g1, g0), g0);   // y=0, both z
        half2 b = __hfma2(fx2, __hsub2(g3, g2), g2);   // y=1, both z
        half2 c = __hfma2(fy2, __hsub2(b, a), a);      // {z0, z1}

        float clo = __low2float(c);
        float chi = __high2float(c);
        float r = fmaf(fz, chi - clo, clo) * INV_VAL_SCALE;

        // Output: write-once stream, evict-first (protect cell table in L2).
        if (!GUARD || valid)
            __stcs(&out[(size_t)p0 * 16 + 32 * k + lane], r);
    }
}

__global__ void __launch_bounds__(256)
encode_kernel(const float* __restrict__ pos, float* __restrict__ out,
              float4 scales, int n)
{
    const int lane = threadIdx.x & 31;
    const int warp = (blockIdx.x * blockDim.x + threadIdx.x) >> 5;
    const int p0 = warp * 16;
    if (p0 >= n) return;

    const int q = lane >> 4;            // point parity within slot
    const int L = (lane >> 2) & 3;      // level
    const int f = lane & 3;             // feature

    const float s = (L < 2) ? (L == 0 ? scales.x : scales.y)
                            : (L == 2 ? scales.z : scales.w);
    const int res  = c_res[L];
    const int res2 = res * res;
    const int off  = c_off[L];
    const __half* cells_f = g_cells_h + f * 8;

    if (p0 + 16 <= n)
        encode_body<false>(pos, out, cells_f, s, res, res2, off, p0, q, lane, n);
    else
        encode_body<true>(pos, out, cells_f, s, res, res2, off, p0, q, lane, n);
}

// ---------------------------------------------------------------- launcher
extern "C" void kernel_launch(void* const* d_in, const int* in_sizes, int n_in,
                              void* d_out, int out_size)
{
    const float* positions = (const float*)d_in[0];
    const float* table = (const float*)d_in[1];
    float* out = (float*)d_out;

    int n = in_sizes[0] / 3;

    // Level scales: double math, rounded to fp32 like JAX's weak promotion.
    double b = 1.3195079565048218;
    double p = 1.0;
    float s[4];
    for (int l = 0; l < 4; ++l) {
        s[l] = (float)(32.0 * p - 1.0);
        p *= b;
    }
    float4 scales = make_float4(s[0], s[1], s[2], s[3]);

    int bb = (NPARAMS * 2 + 255) / 256;
    build_cells<<<bb, 256>>>(table);

    int warps = (n + 15) / 16;
    int blocks = (warps * 32 + 255) / 256;
    encode_kernel<<<blocks, 256>>>(positions, out, scales, n);
}

// round 14
// speedup vs baseline: 1.4730x; 1.1384x over previous
#include <cuda_runtime.h>
#include <cuda_fp16.h>
#include <cuda_bf16.h>

// HashEncoder: 4-level dense-grid trilinear interpolation, F=4.
// R14 = R13 + depth-1 position prefetch under a register cap
// (__launch_bounds__(256,7) -> <=36 regs, 56 warps/SM preserved).
// R10 showed prefetch-without-cap loses via occupancy (40 regs, 63%);
// this isolates the prefetch benefit at full occupancy.
// fp16 cell records (64B/cell, values pre-scaled by 2^12). Per (cell,feature):
// 4 half2 groups g(dy*2+dx) = {c(dx,dy,z0), c(dx,dy,z1)}.
// Encode: 2 points per warp-slot (lane = q*16 + L*4 + f); ONE 16B gather per
// lane per slot -> 4 L1tex wavefronts/point (gather optimum). Positions
// __ldcs (read-once), output __stcs (write-once; protects cell table in L2).
//
// Level meta: res={32,43,56,74}, offsets={0,32768,112280,287896}, total=693120.

#define NPARAMS 693120
#define VAL_SCALE 4096.0f
#define INV_VAL_SCALE (1.0f / 4096.0f)

__device__ __half g_cells_h[NPARAMS * 32];   // 44.4 MB scratch (64B/cell)

__constant__ int c_res[4] = {32, 43, 56, 74};
__constant__ int c_off[4] = {0, 32768, 112280, 287896};

// ---------------------------------------------------------------- preprocess table
// thread t = gbase*2 + fp : builds records for features {2fp, 2fp+1}.
__global__ void __launch_bounds__(256)
build_cells(const float* __restrict__ tab)
{
    int t = blockIdx.x * blockDim.x + threadIdx.x;
    if (t >= NPARAMS * 2) return;

    int gbase = t >> 1;
    int fp = t & 1;

    int L = (gbase >= 32768) + (gbase >= 112280) + (gbase >= 287896);
    int res  = c_res[L];
    int off  = c_off[L];
    int res2 = res * res;
    int local = gbase - off;

    int z   = local / res2;          // padding cells may exceed grid; clamp below
    int rem = local - z * res2;
    int y   = rem / res;
    int x   = rem - y * res;

    float2 v[4][2];                  // [g=dy*2+dx][dz] = (feat 2fp, feat 2fp+1)
#pragma unroll
    for (int g = 0; g < 4; ++g) {
        int xi = min(x + (g & 1), res - 1);
        int yi = min(y + (g >> 1), res - 1);
#pragma unroll
        for (int dz = 0; dz < 2; ++dz) {
            int zi = min(z + dz, res - 1);
            int idx = off + xi + yi * res + zi * res2;
            float2 w = __ldg((const float2*)&tab[idx * 4 + 2 * fp]);
            v[g][dz] = make_float2(w.x * VAL_SCALE, w.y * VAL_SCALE);
        }
    }

    uint4 r0, r1;
    {
        half2 h0 = __floats2half2_rn(v[0][0].x, v[0][1].x);
        half2 h1 = __floats2half2_rn(v[1][0].x, v[1][1].x);
        half2 h2 = __floats2half2_rn(v[2][0].x, v[2][1].x);
        half2 h3 = __floats2half2_rn(v[3][0].x, v[3][1].x);
        r0.x = *(unsigned*)&h0; r0.y = *(unsigned*)&h1;
        r0.z = *(unsigned*)&h2; r0.w = *(unsigned*)&h3;
    }
    {
        half2 h0 = __floats2half2_rn(v[0][0].y, v[0][1].y);
        half2 h1 = __floats2half2_rn(v[1][0].y, v[1][1].y);
        half2 h2 = __floats2half2_rn(v[2][0].y, v[2][1].y);
        half2 h3 = __floats2half2_rn(v[3][0].y, v[3][1].y);
        r1.x = *(unsigned*)&h0; r1.y = *(unsigned*)&h1;
        r1.z = *(unsigned*)&h2; r1.w = *(unsigned*)&h3;
    }

    uint4* dst = (uint4*)g_cells_h;
    dst[gbase * 4 + 2 * fp]     = r0;
    dst[gbase * 4 + 2 * fp + 1] = r1;
}

// ---------------------------------------------------------------- main pass
// Fast path (no guard): depth-1 position prefetch breaks the per-iteration
// serial chain posLDG -> gatherLDG.
__device__ __forceinline__ void
encode_fast(const float* __restrict__ pos, float* __restrict__ out,
            const __half* __restrict__ cells_f, float s,
            int res, int res2, int off,
            int p0, int q, int lane)
{
    const float* pp = pos + 3 * (p0 + q);      // this lane's first point
    float nx = __ldcs(&pp[0]);
    float ny = __ldcs(&pp[1]);
    float nz = __ldcs(&pp[2]);

#pragma unroll
    for (int k = 0; k < 8; ++k) {
        float x = nx, y = ny, z = nz;
        if (k < 7) {                           // prefetch next slot's position
            nx = __ldcs(&pp[6 * (k + 1) + 0]);
            ny = __ldcs(&pp[6 * (k + 1) + 1]);
            nz = __ldcs(&pp[6 * (k + 1) + 2]);
        }

        float px = fmaf(x, s, 0.5f);
        float py = fmaf(y, s, 0.5f);
        float pz = fmaf(z, s, 0.5f);
        int ix = __float2int_rd(px);           // px,py,pz >= 0.5: rd == floor
        int iy = __float2int_rd(py);
        int iz = __float2int_rd(pz);
        float fx = px - __int2float_rn(ix);
        float fy = py - __int2float_rn(iy);
        float fz = pz - __int2float_rn(iz);

        int gbase = off + ix + iy * res + iz * res2;

        uint4 rec = __ldg((const uint4*)(cells_f + (size_t)gbase * 32));
        half2 g0 = *(half2*)&rec.x;            // (dx,dy)=(0,0), {z0,z1}
        half2 g1 = *(half2*)&rec.y;            // (1,0)
        half2 g2 = *(half2*)&rec.z;            // (0,1)
        half2 g3 = *(half2*)&rec.w;            // (1,1)

        half2 fx2 = __float2half2_rn(fx);
        half2 fy2 = __float2half2_rn(fy);

        half2 a = __hfma2(fx2, __hsub2(g1, g0), g0);
        half2 b = __hfma2(fx2, __hsub2(g3, g2), g2);
        half2 c = __hfma2(fy2, __hsub2(b, a), a);    // {z0, z1}

        float clo = __low2float(c);
        float chi = __high2float(c);
        float r = fmaf(fz, chi - clo, clo) * INV_VAL_SCALE;

        __stcs(&out[(size_t)p0 * 16 + 32 * k + lane], r);
    }
}

// Guard path (tail warp only; never taken when n % 16 == 0).
__device__ __forceinline__ void
encode_guard(const float* __restrict__ pos, float* __restrict__ out,
             const __half* __restrict__ cells_f, float s,
             int res, int res2, int off,
             int p0, int q, int lane, int n)
{
    for (int k = 0; k < 8; ++k) {
        int p = p0 + 2 * k + q;
        bool valid = (p < n);
        int pc = valid ? p : (n - 1);

        float x = __ldcs(&pos[3 * pc + 0]);
        float y = __ldcs(&pos[3 * pc + 1]);
        float z = __ldcs(&pos[3 * pc + 2]);

        float px = fmaf(x, s, 0.5f);
        float py = fmaf(y, s, 0.5f);
        float pz = fmaf(z, s, 0.5f);
        int ix = __float2int_rd(px);
        int iy = __float2int_rd(py);
        int iz = __float2int_rd(pz);
        float fx = px - __int2float_rn(ix);
        float fy = py - __int2float_rn(iy);
        float fz = pz - __int2float_rn(iz);

        int gbase = off + ix + iy * res + iz * res2;

        uint4 rec = __ldg((const uint4*)(cells_f + (size_t)gbase * 32));
        half2 g0 = *(half2*)&rec.x;
        half2 g1 = *(half2*)&rec.y;
        half2 g2 = *(half2*)&rec.z;
        half2 g3 = *(half2*)&rec.w;

        half2 fx2 = __float2half2_rn(fx);
        half2 fy2 = __float2half2_rn(fy);

        half2 a = __hfma2(fx2, __hsub2(g1, g0), g0);
        half2 b = __hfma2(fx2, __hsub2(g3, g2), g2);
        half2 c = __hfma2(fy2, __hsub2(b, a), a);

        float clo = __low2float(c);
        float chi = __high2float(c);
        float r = fmaf(fz, chi - clo, clo) * INV_VAL_SCALE;

        if (valid)
            __stcs(&out[(size_t)p0 * 16 + 32 * k + lane], r);
    }
}

__global__ void __launch_bounds__(256, 7)   // caps regs at 36: keeps 56 warps/SM
encode_kernel(const float* __restrict__ pos, float* __restrict__ out,
              float4 scales, int n)
{
    const int lane = threadIdx.x & 31;
    const int warp = (blockIdx.x * blockDim.x + threadIdx.x) >> 5;
    const int p0 = warp * 16;
    if (p0 >= n) return;

    const int q = lane >> 4;            // point parity within slot
    const int L = (lane >> 2) & 3;      // level
    const int f = lane & 3;             // feature

    const float s = (L < 2) ? (L == 0 ? scales.x : scales.y)
                            : (L == 2 ? scales.z : scales.w);
    const int res  = c_res[L];
    const int res2 = res * res;
    const int off  = c_off[L];
    const __half* cells_f = g_cells_h + f * 8;

    if (p0 + 16 <= n)
        encode_fast(pos, out, cells_f, s, res, res2, off, p0, q, lane);
    else
        encode_guard(pos, out, cells_f, s, res, res2, off, p0, q, lane, n);
}

// ---------------------------------------------------------------- launcher
extern "C" void kernel_launch(void* const* d_in, const int* in_sizes, int n_in,
                              void* d_out, int out_size)
{
    const float* positions = (const float*)d_in[0];
    const float* table = (const float*)d_in[1];
    float* out = (float*)d_out;

    int n = in_sizes[0] / 3;

    // Level scales: double math, rounded to fp32 like JAX's weak promotion.
    double b = 1.3195079565048218;
    double p = 1.0;
    float s[4];
    for (int l = 0; l < 4; ++l) {
        s[l] = (float)(32.0 * p - 1.0);
        p *= b;
    }
    float4 scales = make_float4(s[0], s[1], s[2], s[3]);

    int bb = (NPARAMS * 2 + 255) / 256;
    build_cells<<<bb, 256>>>(table);

    int warps = (n + 15) / 16;
    int blocks = (warps * 32 + 255) / 256;
    encode_kernel<<<blocks, 256>>>(positions, out, scales, n);
}